// round 7
// baseline (speedup 1.0000x reference)
#include <cuda_runtime.h>
#include <cuda_bf16.h>
#include <math.h>
#include <cstdint>

// ---------------- problem constants ----------------
#define HH      56
#define WW2     56
#define CC      192
#define NHEADS  6
#define WSZ     7
#define SSHIFT  3
#define HIDDIM  768
#define NTOK    49
#define HDIM    32
#define NWINS   4096
#define TTOT    200704
#define SCALEQ  0.17677669529663687f

// ---------------- scratch ----------------
__device__ float  g_X  [(size_t)TTOT * CC];
__device__ float  g_XW [(size_t)TTOT * CC];
__device__ float  g_QKV[(size_t)TTOT * 3 * CC];
__device__ float  g_H1 [(size_t)TTOT * HIDDIM];
__device__ float2 g_ST [TTOT];                    // per-token (mu, rstd)

// split weights, transposed to [N][K] bf16 (hi + lo)
__device__ __nv_bfloat16 g_Wqkv_h[2 * 576 * 192];
__device__ __nv_bfloat16 g_Wqkv_l[2 * 576 * 192];
__device__ __nv_bfloat16 g_Wprj_h[2 * 192 * 192];
__device__ __nv_bfloat16 g_Wprj_l[2 * 192 * 192];
__device__ __nv_bfloat16 g_Wfc1_h[2 * 768 * 192];
__device__ __nv_bfloat16 g_Wfc1_l[2 * 768 * 192];
__device__ __nv_bfloat16 g_Wfc2_h[2 * 192 * 768];
__device__ __nv_bfloat16 g_Wfc2_l[2 * 192 * 768];

// ====================== combined weight transpose + split (one layer) ======================
__global__ __launch_bounds__(256) void wsplit_layer_kernel(
    const float* __restrict__ qkvw, const float* __restrict__ projw,
    const float* __restrict__ fc1w, const float* __restrict__ fc2w,
    __nv_bfloat16* __restrict__ qh, __nv_bfloat16* __restrict__ ql,
    __nv_bfloat16* __restrict__ ph, __nv_bfloat16* __restrict__ pl,
    __nv_bfloat16* __restrict__ f1h, __nv_bfloat16* __restrict__ f1l,
    __nv_bfloat16* __restrict__ f2h, __nv_bfloat16* __restrict__ f2l)
{
    int idx = blockIdx.x * 256 + threadIdx.x;
    const float* W; __nv_bfloat16 *Hp, *Lp; int K, N, off;
    if (idx < 110592)       { W = qkvw; Hp = qh;  Lp = ql;  K = 192; N = 576; off = idx; }
    else if (idx < 147456)  { W = projw; Hp = ph; Lp = pl;  K = 192; N = 192; off = idx - 110592; }
    else if (idx < 294912)  { W = fc1w; Hp = f1h; Lp = f1l; K = 192; N = 768; off = idx - 147456; }
    else if (idx < 442368)  { W = fc2w; Hp = f2h; Lp = f2l; K = 768; N = 192; off = idx - 294912; }
    else return;
    int k = off / N, n = off - k * N;
    float v = W[off];
    __nv_bfloat16 h = __float2bfloat16_rn(v);
    __nv_bfloat16 l = __float2bfloat16_rn(v - __bfloat162float(h));
    Hp[(size_t)n * K + k] = h;
    Lp[(size_t)n * K + k] = l;
}

// ====================== LN stats (per token) ======================
__global__ __launch_bounds__(256) void lnstats_kernel(
    const float* __restrict__ src, float2* __restrict__ st)
{
    int warp = threadIdx.x >> 5, lane = threadIdx.x & 31;
    int m = blockIdx.x * 8 + warp;
    const float* xp = src + (size_t)m * CC;
    float s = 0.f, ss = 0.f;
    #pragma unroll
    for (int j = 0; j < 6; j++) { float v = xp[lane + 32*j]; s += v; ss += v*v; }
    #pragma unroll
    for (int o = 16; o > 0; o >>= 1) {
        s  += __shfl_xor_sync(0xffffffffu, s,  o);
        ss += __shfl_xor_sync(0xffffffffu, ss, o);
    }
    if (lane == 0) {
        float mu = s * (1.f / CC);
        float rstd = rsqrtf(ss * (1.f / CC) - mu * mu + 1e-5f);
        st[m] = make_float2(mu, rstd);
    }
}

// ====================== window attention ======================
__global__ __launch_bounds__(128) void attn_kernel(
    const float* __restrict__ qkv, float* __restrict__ outp,
    const float* __restrict__ rpb, int shifted)
{
    int win = blockIdx.x / NHEADS;
    int hd  = blockIdx.x % NHEADS;
    __shared__ float q[NTOK][HDIM + 1];
    __shared__ float k[NTOK][HDIM + 1];
    __shared__ float v[NTOK][HDIM + 1];
    __shared__ float sc[NTOK][52];
    __shared__ int   lab[NTOK];
    int tid = threadIdx.x;

    const float* base = qkv + (size_t)win * NTOK * 576 + hd * HDIM;
    for (int idx = tid; idx < NTOK * HDIM; idx += 128) {
        int i = idx >> 5, d = idx & 31;
        const float* row = base + (size_t)i * 576 + d;
        q[i][d] = row[0]   * SCALEQ;
        k[i][d] = row[192];
        v[i][d] = row[384];
    }
    if (shifted && tid < NTOK) {
        int wl = win & 63;
        int h = (wl >> 3) * WSZ + tid / WSZ;
        int w = (wl & 7)  * WSZ + tid % WSZ;
        int rc = (h < HH  - WSZ) ? 0 : ((h < HH  - SSHIFT) ? 1 : 2);
        int cc = (w < WW2 - WSZ) ? 0 : ((w < WW2 - SSHIFT) ? 1 : 2);
        lab[tid] = rc * 3 + cc;
    }
    __syncthreads();

    for (int idx = tid; idx < NTOK * NTOK; idx += 128) {
        int i = idx / NTOK, j = idx - i * NTOK;
        float acc = 0.f;
        #pragma unroll
        for (int d = 0; d < HDIM; d++) acc += q[i][d] * k[j][d];
        int ridx = (i / WSZ - j / WSZ + WSZ - 1) * (2 * WSZ - 1)
                 + (i % WSZ - j % WSZ + WSZ - 1);
        acc += rpb[ridx * NHEADS + hd];
        if (shifted && lab[i] != lab[j]) acc -= 100.f;
        sc[i][j] = acc;
    }
    __syncthreads();

    int warp = tid >> 5, lane = tid & 31;
    for (int i = warp; i < NTOK; i += 4) {
        float a0 = (lane < NTOK)      ? sc[i][lane]      : -1e30f;
        float a1 = (lane + 32 < NTOK) ? sc[i][lane + 32] : -1e30f;
        float mx = fmaxf(a0, a1);
        #pragma unroll
        for (int o = 16; o > 0; o >>= 1) mx = fmaxf(mx, __shfl_xor_sync(0xffffffffu, mx, o));
        float e0 = (lane < NTOK)      ? __expf(a0 - mx) : 0.f;
        float e1 = (lane + 32 < NTOK) ? __expf(a1 - mx) : 0.f;
        float sum = e0 + e1;
        #pragma unroll
        for (int o = 16; o > 0; o >>= 1) sum += __shfl_xor_sync(0xffffffffu, sum, o);
        float inv = 1.f / sum;
        if (lane < NTOK)      sc[i][lane]      = e0 * inv;
        if (lane + 32 < NTOK) sc[i][lane + 32] = e1 * inv;
    }
    __syncthreads();

    float* obase = outp + (size_t)win * NTOK * CC + hd * HDIM;
    for (int idx = tid; idx < NTOK * HDIM; idx += 128) {
        int i = idx >> 5, d = idx & 31;
        float acc = 0.f;
        #pragma unroll
        for (int j = 0; j < NTOK; j++) acc += sc[i][j] * v[j][d];
        obase[(size_t)i * CC + d] = acc;
    }
}

// ====================== bf16 hi/lo tensor-core GEMM ======================
// BM=128, BN=64, BK=32, 256 threads (8 warps, 4x2 warp grid, warp tile 32x32).
// 3 passes: Ah*Bh + Ah*Bl + Al*Bh.
// EPI:  0 store; 1 win-reverse(+unshift) residual (out = resid + val);
//       2 exact GELU store; 3 residual (out = resid + val, token order)
// LNM:  0 raw A rows; 1 LN in token order; 2 LN + window(+shift) gather (K must be 192)
#define BK      32
#define BN      64
#define STRD    40
#define A_SZ    (128 * STRD)
#define B_SZ    (BN * STRD)
#define OFF_AHI 0
#define OFF_ALO A_SZ
#define OFF_BHI (2 * A_SZ)
#define OFF_BLO (2 * A_SZ + B_SZ)
#define STAGE   (2 * A_SZ + 2 * B_SZ)
#define GSMEM   (2 * STAGE * 2)

__device__ __forceinline__ void split8(const float* f, uint4& hi, uint4& lo)
{
    uint32_t hb[8], lb[8];
    #pragma unroll
    for (int i = 0; i < 8; i++) {
        __nv_bfloat16 h = __float2bfloat16_rn(f[i]);
        __nv_bfloat16 l = __float2bfloat16_rn(f[i] - __bfloat162float(h));
        hb[i] = (uint32_t)__bfloat16_as_ushort(h);
        lb[i] = (uint32_t)__bfloat16_as_ushort(l);
    }
    hi.x = hb[0] | (hb[1] << 16); hi.y = hb[2] | (hb[3] << 16);
    hi.z = hb[4] | (hb[5] << 16); hi.w = hb[6] | (hb[7] << 16);
    lo.x = lb[0] | (lb[1] << 16); lo.y = lb[2] | (lb[3] << 16);
    lo.z = lb[4] | (lb[5] << 16); lo.w = lb[6] | (lb[7] << 16);
}

__device__ __forceinline__ void mma16816(float* c, const uint32_t* a, const uint32_t* b)
{
    asm volatile(
        "mma.sync.aligned.m16n8k16.row.col.f32.bf16.bf16.f32 "
        "{%0,%1,%2,%3}, {%4,%5,%6,%7}, {%8,%9}, {%0,%1,%2,%3};"
        : "+f"(c[0]), "+f"(c[1]), "+f"(c[2]), "+f"(c[3])
        : "r"(a[0]), "r"(a[1]), "r"(a[2]), "r"(a[3]), "r"(b[0]), "r"(b[1]));
}

__device__ __forceinline__ void cp_async16(void* smem, const void* gmem)
{
    uint32_t sa = (uint32_t)__cvta_generic_to_shared(smem);
    asm volatile("cp.async.cg.shared.global [%0], [%1], 16;" :: "r"(sa), "l"(gmem));
}
#define CP_COMMIT()  asm volatile("cp.async.commit_group;")
#define CP_WAIT0()   asm volatile("cp.async.wait_group 0;")

template<int EPI, int LNM>
__global__ __launch_bounds__(256, 2) void mma_gemm_kernel(
    const float* __restrict__ A,
    const __nv_bfloat16* __restrict__ Bhi, const __nv_bfloat16* __restrict__ Blo,
    const float* __restrict__ bias, float* __restrict__ Cout,
    const float* __restrict__ resid,
    const float2* __restrict__ stats,
    const float* __restrict__ lng, const float* __restrict__ lnb,
    int N, int K, int shifted)
{
    extern __shared__ __nv_bfloat16 sm[];
    int tid = threadIdx.x;
    int wid = tid >> 5, lane = tid & 31;
    int wr = wid >> 1, wc = wid & 1;
    int g = lane >> 2, t2 = (lane & 3) * 2;
    int m0 = blockIdx.y * 128, n0 = blockIdx.x * BN;

    // ---- A source row mapping ----
    int ar = tid >> 1, ahf = tid & 1;
    size_t tok;
    {
        int m = m0 + ar;
        if (LNM == 2) {
            int win = m / NTOK, n = m - win * NTOK;
            int b = win >> 6, wl = win & 63;
            int hs = (wl >> 3) * WSZ + n / WSZ;
            int ws = (wl & 7)  * WSZ + n % WSZ;
            if (shifted) { hs = (hs + SSHIFT) % HH; ws = (ws + SSHIFT) % WW2; }
            tok = ((size_t)b * HH + hs) * WW2 + ws;
        } else {
            tok = (size_t)m;
        }
    }
    float mu = 0.f, rstd = 1.f;
    if (LNM) { float2 st = stats[tok]; mu = st.x; rstd = st.y; }
    const float* Ap = A + tok * K + ahf * 16;

    // ---- B source ----
    int br = tid >> 2, bc = tid & 3;
    const __nv_bfloat16* Bph = Bhi + (size_t)(n0 + br) * K + bc * 8;
    const __nv_bfloat16* Bpl = Blo + (size_t)(n0 + br) * K + bc * 8;

    float acc[2][4][4];
    #pragma unroll
    for (int mt = 0; mt < 2; mt++)
        #pragma unroll
        for (int nt = 0; nt < 4; nt++)
            #pragma unroll
            for (int r = 0; r < 4; r++) acc[mt][nt][r] = 0.f;

    // prologue: issue B(0) cp.async, prefetch A(0) regs
    {
        __nv_bfloat16* st0 = sm;
        cp_async16(&st0[OFF_BHI + br * STRD + bc * 8], Bph);
        cp_async16(&st0[OFF_BLO + br * STRD + bc * 8], Bpl);
        CP_COMMIT();
    }
    float pa[16];
    #pragma unroll
    for (int j4 = 0; j4 < 4; j4++)
        *(float4*)&pa[j4 * 4] = *(const float4*)(Ap + j4 * 4);

    int KT = K >> 5;
    for (int kt = 0; kt < KT; kt++) {
        __nv_bfloat16* st = sm + (kt & 1) * STAGE;
        // ---- STS A (with optional LN) ----
        {
            float f[16];
            if (LNM) {
                int c0 = kt * 32 + ahf * 16;
                float lg[16], lb2[16];
                #pragma unroll
                for (int j4 = 0; j4 < 4; j4++) {
                    *(float4*)&lg[j4 * 4]  = *(const float4*)(lng + c0 + j4 * 4);
                    *(float4*)&lb2[j4 * 4] = *(const float4*)(lnb + c0 + j4 * 4);
                }
                #pragma unroll
                for (int j = 0; j < 16; j++)
                    f[j] = (pa[j] - mu) * rstd * lg[j] + lb2[j];
            } else {
                #pragma unroll
                for (int j = 0; j < 16; j++) f[j] = pa[j];
            }
            uint4 h0, l0, h1, l1;
            split8(f, h0, l0);
            split8(f + 8, h1, l1);
            uint4* dh = (uint4*)&st[OFF_AHI + ar * STRD + ahf * 16];
            uint4* dl = (uint4*)&st[OFF_ALO + ar * STRD + ahf * 16];
            dh[0] = h0; dh[1] = h1;
            dl[0] = l0; dl[1] = l1;
        }
        CP_WAIT0();
        __syncthreads();
        // issue next B tile into other buffer; prefetch next A regs
        if (kt + 1 < KT) {
            __nv_bfloat16* stn = sm + ((kt + 1) & 1) * STAGE;
            cp_async16(&stn[OFF_BHI + br * STRD + bc * 8], Bph + (kt + 1) * 32);
            cp_async16(&stn[OFF_BLO + br * STRD + bc * 8], Bpl + (kt + 1) * 32);
            CP_COMMIT();
            const float* ap2 = Ap + (kt + 1) * 32;
            #pragma unroll
            for (int j4 = 0; j4 < 4; j4++)
                *(float4*)&pa[j4 * 4] = *(const float4*)(ap2 + j4 * 4);
        }
        // ---- compute ----
        const __nv_bfloat16* cs = sm + (kt & 1) * STAGE;
        #pragma unroll
        for (int kk = 0; kk < 32; kk += 16) {
            uint32_t afh[2][4], afl[2][4], bfh[4][2], bfl[4][2];
            #pragma unroll
            for (int mt = 0; mt < 2; mt++) {
                int r0 = (wr * 32 + mt * 16 + g) * STRD + kk + t2;
                afh[mt][0] = *(const uint32_t*)&cs[OFF_AHI + r0];
                afh[mt][1] = *(const uint32_t*)&cs[OFF_AHI + r0 + 8 * STRD];
                afh[mt][2] = *(const uint32_t*)&cs[OFF_AHI + r0 + 8];
                afh[mt][3] = *(const uint32_t*)&cs[OFF_AHI + r0 + 8 * STRD + 8];
            }
            #pragma unroll
            for (int nt = 0; nt < 4; nt++) {
                int rb = (wc * 32 + nt * 8 + g) * STRD + kk + t2;
                bfh[nt][0] = *(const uint32_t*)&cs[OFF_BHI + rb];
                bfh[nt][1] = *(const uint32_t*)&cs[OFF_BHI + rb + 8];
            }
            #pragma unroll
            for (int mt = 0; mt < 2; mt++)
                #pragma unroll
                for (int nt = 0; nt < 4; nt++)
                    mma16816(acc[mt][nt], afh[mt], bfh[nt]);
            #pragma unroll
            for (int nt = 0; nt < 4; nt++) {
                int rb = (wc * 32 + nt * 8 + g) * STRD + kk + t2;
                bfl[nt][0] = *(const uint32_t*)&cs[OFF_BLO + rb];
                bfl[nt][1] = *(const uint32_t*)&cs[OFF_BLO + rb + 8];
            }
            #pragma unroll
            for (int mt = 0; mt < 2; mt++)
                #pragma unroll
                for (int nt = 0; nt < 4; nt++)
                    mma16816(acc[mt][nt], afh[mt], bfl[nt]);
            #pragma unroll
            for (int mt = 0; mt < 2; mt++) {
                int r0 = (wr * 32 + mt * 16 + g) * STRD + kk + t2;
                afl[mt][0] = *(const uint32_t*)&cs[OFF_ALO + r0];
                afl[mt][1] = *(const uint32_t*)&cs[OFF_ALO + r0 + 8 * STRD];
                afl[mt][2] = *(const uint32_t*)&cs[OFF_ALO + r0 + 8];
                afl[mt][3] = *(const uint32_t*)&cs[OFF_ALO + r0 + 8 * STRD + 8];
            }
            #pragma unroll
            for (int mt = 0; mt < 2; mt++)
                #pragma unroll
                for (int nt = 0; nt < 4; nt++)
                    mma16816(acc[mt][nt], afl[mt], bfh[nt]);
        }
        __syncthreads();
    }

    // ---- epilogue ----
    #pragma unroll
    for (int mt = 0; mt < 2; mt++) {
        #pragma unroll
        for (int hf = 0; hf < 2; hf++) {
            int m = m0 + wr * 32 + mt * 16 + hf * 8 + g;
            size_t orow;
            if (EPI == 1) {
                int win = m / NTOK, n = m - win * NTOK;
                int b = win >> 6, wl = win & 63;
                int hs = (wl >> 3) * WSZ + n / WSZ;
                int ws = (wl & 7)  * WSZ + n % WSZ;
                if (shifted) { hs = (hs + SSHIFT) % HH; ws = (ws + SSHIFT) % WW2; }
                orow = (((size_t)b * HH + hs) * WW2 + ws) * CC;
            } else if (EPI == 3) {
                orow = (size_t)m * CC;
            } else {
                orow = (size_t)m * N;
            }
            #pragma unroll
            for (int nt = 0; nt < 4; nt++) {
                int n = n0 + wc * 32 + nt * 8 + t2;
                float vx = acc[mt][nt][hf * 2 + 0] + bias[n];
                float vy = acc[mt][nt][hf * 2 + 1] + bias[n + 1];
                if (EPI == 2) {
                    vx = 0.5f * vx * (1.f + erff(vx * 0.70710678118654752f));
                    vy = 0.5f * vy * (1.f + erff(vy * 0.70710678118654752f));
                }
                if (EPI == 0 || EPI == 2) {
                    float2 v = {vx, vy};
                    *(float2*)&Cout[orow + n] = v;
                } else {
                    float2 r = *(const float2*)&resid[orow + n];
                    float2 v = {r.x + vx, r.y + vy};
                    *(float2*)&Cout[orow + n] = v;
                }
            }
        }
    }
}

// ====================== launch ======================
extern "C" void kernel_launch(void* const* d_in, const int* in_sizes, int n_in,
                              void* d_out, int out_size)
{
    (void)in_sizes; (void)n_in; (void)out_size;
    const float* x     = (const float*)d_in[0];
    const float* ln1g  = (const float*)d_in[1];
    const float* ln1b  = (const float*)d_in[2];
    const float* qkvw  = (const float*)d_in[3];
    const float* qkvb  = (const float*)d_in[4];
    const float* rpb   = (const float*)d_in[5];
    const float* projw = (const float*)d_in[6];
    const float* projb = (const float*)d_in[7];
    const float* ln2g  = (const float*)d_in[8];
    const float* ln2b  = (const float*)d_in[9];
    const float* fc1w  = (const float*)d_in[10];
    const float* fc1b  = (const float*)d_in[11];
    const float* fc2w  = (const float*)d_in[12];
    const float* fc2b  = (const float*)d_in[13];
    float* out = (float*)d_out;

    float *X, *XW, *QKV, *H1; float2* ST;
    cudaGetSymbolAddress((void**)&X,   g_X);
    cudaGetSymbolAddress((void**)&XW,  g_XW);
    cudaGetSymbolAddress((void**)&QKV, g_QKV);
    cudaGetSymbolAddress((void**)&H1,  g_H1);
    cudaGetSymbolAddress((void**)&ST,  g_ST);

    __nv_bfloat16 *Wqh, *Wql, *Wph, *Wpl, *W1h, *W1l, *W2h, *W2l;
    cudaGetSymbolAddress((void**)&Wqh, g_Wqkv_h); cudaGetSymbolAddress((void**)&Wql, g_Wqkv_l);
    cudaGetSymbolAddress((void**)&Wph, g_Wprj_h); cudaGetSymbolAddress((void**)&Wpl, g_Wprj_l);
    cudaGetSymbolAddress((void**)&W1h, g_Wfc1_h); cudaGetSymbolAddress((void**)&W1l, g_Wfc1_l);
    cudaGetSymbolAddress((void**)&W2h, g_Wfc2_h); cudaGetSymbolAddress((void**)&W2l, g_Wfc2_l);

    cudaFuncSetAttribute(mma_gemm_kernel<0,2>, cudaFuncAttributeMaxDynamicSharedMemorySize, GSMEM);
    cudaFuncSetAttribute(mma_gemm_kernel<1,0>, cudaFuncAttributeMaxDynamicSharedMemorySize, GSMEM);
    cudaFuncSetAttribute(mma_gemm_kernel<2,1>, cudaFuncAttributeMaxDynamicSharedMemorySize, GSMEM);
    cudaFuncSetAttribute(mma_gemm_kernel<3,0>, cudaFuncAttributeMaxDynamicSharedMemorySize, GSMEM);

    // weight transpose + hi/lo split (one launch per layer)
    for (int layer = 0; layer < 2; layer++) {
        size_t oq = (size_t)layer * 192 * 576;
        size_t op = (size_t)layer * 192 * 192;
        size_t o1 = (size_t)layer * 192 * 768;
        size_t o2 = (size_t)layer * 768 * 192;
        wsplit_layer_kernel<<<1728, 256>>>(
            qkvw + oq, projw + op, fc1w + o1, fc2w + o2,
            Wqh + oq, Wql + oq, Wph + op, Wpl + op,
            W1h + o1, W1l + o1, W2h + o2, W2l + o2);
    }

    const int MB = TTOT / 128;  // 1568
    for (int layer = 0; layer < 2; layer++) {
        int shifted = layer & 1;
        size_t oq = (size_t)layer * 192 * 576;
        size_t op = (size_t)layer * 192 * 192;
        size_t o1 = (size_t)layer * 192 * 768;
        size_t o2 = (size_t)layer * 768 * 192;
        const float* pre = (layer == 0) ? x : X;   // pre-LN1 residual stream
        float* fc2_out   = (layer == 0) ? X : out; // final layer writes d_out

        // LN1 stats on the residual stream
        lnstats_kernel<<<TTOT / 8, 256>>>(pre, ST);
        // QKV GEMM: LN + window(+shift) gather fused into A-loader
        mma_gemm_kernel<0, 2><<<dim3(576 / BN, MB), 256, GSMEM>>>(
            pre, Wqh + oq, Wql + oq, qkvb + layer * 576, QKV,
            nullptr, ST, ln1g + layer * CC, ln1b + layer * CC, 576, 192, shifted);
        // attention -> XW (window order)
        attn_kernel<<<NWINS * NHEADS, 128>>>(QKV, XW, rpb + layer * 169 * NHEADS, shifted);
        // proj + window-reverse(+unshift) + residual (reads pre, writes X)
        mma_gemm_kernel<1, 0><<<dim3(192 / BN, MB), 256, GSMEM>>>(
            XW, Wph + op, Wpl + op, projb + layer * CC, X,
            pre, nullptr, nullptr, nullptr, 192, 192, shifted);
        // LN2 stats on X
        lnstats_kernel<<<TTOT / 8, 256>>>(X, ST);
        // fc1 + GELU, LN fused (token order)
        mma_gemm_kernel<2, 1><<<dim3(768 / BN, MB), 256, GSMEM>>>(
            X, W1h + o1, W1l + o1, fc1b + layer * HIDDIM, H1,
            nullptr, ST, ln2g + layer * CC, ln2b + layer * CC, 768, 192, 0);
        // fc2 + residual (reads X; layer1 writes straight to d_out)
        mma_gemm_kernel<3, 0><<<dim3(192 / BN, MB), 256, GSMEM>>>(
            H1, W2h + o2, W2l + o2, fc2b + layer * CC, fc2_out,
            X, nullptr, nullptr, nullptr, 192, 768, 0);
    }
}